// round 2
// baseline (speedup 1.0000x reference)
#include <cuda_runtime.h>
#include <math.h>

#define NTOK 204800      // 4096 * 50
#define BATCH 4096
#define SEQL 50
#define D 200
#define DP 256
#define NB 3
#define NEGVAL (-4294967295.0f)

// ---------------- scratch (static device allocations) ----------------
__device__ float g_X[(size_t)NTOK * DP];   // current activations (padded)
__device__ float g_Y[(size_t)NTOK * DP];   // MHA output / FFN residual
__device__ float g_Q[(size_t)NTOK * DP];
__device__ float g_K[(size_t)NTOK * DP];
__device__ float g_V[(size_t)NTOK * DP];
__device__ float g_W[15 * DP * DP];        // padded weights: per block {Wq,Wk,Wv,W1,W2}

// ---------------- embed: X[n, d] = emb[tokens[n], d], pad to 256 ----------------
__global__ void __launch_bounds__(256) embed_kernel(const int* __restrict__ tokens,
                                                    const float* __restrict__ emb,
                                                    float* __restrict__ X) {
    int n = blockIdx.x;
    int d = threadIdx.x;
    int tok = tokens[n];
    X[(size_t)n * DP + d] = (d < D) ? emb[(size_t)tok * D + d] : 0.0f;
}

// ---------------- pad weights 200x200 -> 256x256 ----------------
__global__ void __launch_bounds__(256) pad_w_kernel(const float* __restrict__ Wq,
                                                    const float* __restrict__ Wk,
                                                    const float* __restrict__ Wv,
                                                    const float* __restrict__ W1,
                                                    const float* __restrict__ W2,
                                                    float* __restrict__ Wpad) {
    int wi = blockIdx.x;            // 0..14
    int i = wi / 5, j = wi % 5;
    const float* srcs[5] = {Wq, Wk, Wv, W1, W2};
    const float* src = srcs[j] + (size_t)i * D * D;
    int r = blockIdx.y, c = threadIdx.x;
    Wpad[(size_t)wi * DP * DP + r * DP + c] =
        (r < D && c < D) ? src[r * D + c] : 0.0f;
}

// ---------------- fp32 SGEMM: C[M,256] = act(A[M,256] @ W[256,256] + bias) ----------------
// 128x128 tile, BK=8, 256 threads, 8x8 per thread, register-prefetch pipeline.
__global__ void __launch_bounds__(256) gemm_kernel(const float* __restrict__ A,
                                                   const float* __restrict__ B,
                                                   const float* __restrict__ bias,
                                                   float* __restrict__ C,
                                                   int relu) {
    __shared__ float As[8][132];   // transposed A tile, padded
    __shared__ float Bs[8][128];

    const int bm = blockIdx.y * 128;
    const int bn = blockIdx.x * 128;
    const int t = threadIdx.x;

    const int arow = t >> 1;            // 0..127
    const int acol = (t & 1) * 4;       // 0 or 4
    const int brow = t >> 5;            // 0..7
    const int bcol = (t & 31) * 4;      // 0..124
    const int ty = t >> 4;              // 0..15
    const int tx = t & 15;              // 0..15

    float acc[8][8];
#pragma unroll
    for (int i = 0; i < 8; i++)
#pragma unroll
        for (int j = 0; j < 8; j++) acc[i][j] = 0.0f;

    const float* Aptr = A + (size_t)(bm + arow) * DP + acol;
    const float* Bptr = B + (size_t)brow * DP + bn + bcol;

    // prologue: fetch first tile into registers
    float4 av = *(const float4*)(Aptr);
    float4 bv = *(const float4*)(Bptr);

#pragma unroll 1
    for (int k0 = 0; k0 < DP; k0 += 8) {
        As[acol + 0][arow] = av.x;
        As[acol + 1][arow] = av.y;
        As[acol + 2][arow] = av.z;
        As[acol + 3][arow] = av.w;
        *(float4*)&Bs[brow][bcol] = bv;
        __syncthreads();

        // prefetch next k-tile while computing this one
        if (k0 + 8 < DP) {
            av = *(const float4*)(Aptr + k0 + 8);
            bv = *(const float4*)(Bptr + (size_t)(k0 + 8) * DP);
        }

#pragma unroll
        for (int kk = 0; kk < 8; kk++) {
            float a[8], b[8];
#pragma unroll
            for (int i = 0; i < 8; i++) a[i] = As[kk][ty * 8 + i];
#pragma unroll
            for (int j = 0; j < 8; j++) b[j] = Bs[kk][tx * 8 + j];
#pragma unroll
            for (int i = 0; i < 8; i++)
#pragma unroll
                for (int j = 0; j < 8; j++) acc[i][j] += a[i] * b[j];
        }
        __syncthreads();
    }

#pragma unroll
    for (int i = 0; i < 8; i++) {
        int m = bm + ty * 8 + i;
        float vals[8];
#pragma unroll
        for (int j = 0; j < 8; j++) {
            int n = bn + tx * 8 + j;
            float v = acc[i][j] + ((n < D) ? bias[n] : 0.0f);
            if (relu) v = fmaxf(v, 0.0f);
            vals[j] = v;
        }
        float* cp = C + (size_t)m * DP + bn + tx * 8;
        *(float4*)(cp + 0) = make_float4(vals[0], vals[1], vals[2], vals[3]);
        *(float4*)(cp + 4) = make_float4(vals[4], vals[5], vals[6], vals[7]);
    }
}

// ---------------- attention: one CTA per batch ----------------
// smem layout (floats): Qs[50*200] (reused as Vs) | Ks[50*200] | S[50*52] | km[50]
__global__ void __launch_bounds__(256) attn_kernel(const float* __restrict__ Qg,
                                                   const float* __restrict__ Kg,
                                                   const float* __restrict__ Vg,
                                                   const float* __restrict__ Xg,
                                                   float* __restrict__ Og) {
    extern __shared__ float sm[];
    float* Qs = sm;                 // 10000
    float* Ks = sm + 10000;         // 10000
    float* S  = sm + 20000;         // 2600 (row stride 52)
    float* km = sm + 22600;         // 50

    const int b = blockIdx.x;
    const int t = threadIdx.x;
    const int base = b * SEQL;
    const int w = t >> 5, lane = t & 31;

    // stage Q, K (real 200 cols only)
    for (int idx = t; idx < SEQL * D; idx += 256) {
        int l = idx / D, d = idx - l * D;
        Qs[idx] = Qg[(size_t)(base + l) * DP + d];
        Ks[idx] = Kg[(size_t)(base + l) * DP + d];
    }
    // masks from row-sums of x (block input)
    for (int l = w; l < SEQL; l += 8) {
        const float* xr = Xg + (size_t)(base + l) * DP;
        float s = 0.0f;
        for (int d = lane; d < D; d += 32) s += xr[d];
#pragma unroll
        for (int o = 16; o > 0; o >>= 1) s += __shfl_xor_sync(0xffffffffu, s, o);
        if (lane == 0) km[l] = (s == 0.0f) ? 0.0f : 1.0f;
    }
    __syncthreads();

    const float scale = 0.07071067811865475f;   // 1/sqrt(200)
    for (int p = t; p < SEQL * SEQL; p += 256) {
        int q = p / SEQL, k = p - q * SEQL;
        const float* qp = Qs + q * D;
        const float* kp = Ks + k * D;
        float acc = 0.0f;
#pragma unroll 4
        for (int d = 0; d < D; d++) acc += qp[d] * kp[d];
        S[q * 52 + k] = (km[k] == 0.0f) ? NEGVAL : acc * scale;
    }
    __syncthreads();

    // softmax per query row (warp per row)
    for (int q = w; q < SEQL; q += 8) {
        float s1 = S[q * 52 + lane];
        bool v2 = (lane + 32) < SEQL;
        float s2 = v2 ? S[q * 52 + lane + 32] : -INFINITY;
        float m = fmaxf(s1, s2);
#pragma unroll
        for (int o = 16; o > 0; o >>= 1) m = fmaxf(m, __shfl_xor_sync(0xffffffffu, m, o));
        float e1 = expf(s1 - m);
        float e2 = v2 ? expf(s2 - m) : 0.0f;
        float su = e1 + e2;
#pragma unroll
        for (int o = 16; o > 0; o >>= 1) su += __shfl_xor_sync(0xffffffffu, su, o);
        float inv = km[q] / su;
        S[q * 52 + lane] = e1 * inv;
        if (v2) S[q * 52 + lane + 32] = e2 * inv;
    }
    float* Vs = Qs;   // Q no longer needed
    for (int idx = t; idx < SEQL * D; idx += 256) {
        int l = idx / D, d = idx - l * D;
        Vs[idx] = Vg[(size_t)(base + l) * DP + d];
    }
    __syncthreads();

    // out[q,d] = sum_k S[q,k] * V[k,d] + x[q,d]   (pads -> 0)
    const int d = t;
    for (int q = 0; q < SEQL; q++) {
        float o;
        if (d < D) {
            float acc = 0.0f;
#pragma unroll
            for (int k = 0; k < SEQL; k++) acc += S[q * 52 + k] * Vs[k * D + d];
            o = acc + Xg[(size_t)(base + q) * DP + d];
        } else {
            o = 0.0f;
        }
        Og[(size_t)(base + q) * DP + d] = o;
    }
}

// ---------------- layernorm(h2)*g + b + resid ----------------
__global__ void __launch_bounds__(256) ln_res_kernel(const float* __restrict__ h2,
                                                     const float* __restrict__ resid,
                                                     const float* __restrict__ g,
                                                     const float* __restrict__ bln,
                                                     float* __restrict__ out) {
    const int row = blockIdx.x;
    const int d = threadIdx.x;
    const int w = d >> 5, lane = d & 31;
    __shared__ float red[8];
    __shared__ float bc1, bc2;

    float v = (d < D) ? h2[(size_t)row * DP + d] : 0.0f;

    float s = v;
#pragma unroll
    for (int o = 16; o > 0; o >>= 1) s += __shfl_xor_sync(0xffffffffu, s, o);
    if (lane == 0) red[w] = s;
    __syncthreads();
    if (d == 0) {
        float tt = 0.0f;
#pragma unroll
        for (int i = 0; i < 8; i++) tt += red[i];
        bc1 = tt;
    }
    __syncthreads();
    float mu = bc1 * (1.0f / D);
    float diff = (d < D) ? (v - mu) : 0.0f;

    float s2 = diff * diff;
#pragma unroll
    for (int o = 16; o > 0; o >>= 1) s2 += __shfl_xor_sync(0xffffffffu, s2, o);
    if (lane == 0) red[w] = s2;
    __syncthreads();
    if (d == 0) {
        float tt = 0.0f;
#pragma unroll
        for (int i = 0; i < 8; i++) tt += red[i];
        bc2 = tt;
    }
    __syncthreads();
    float var = bc2 * (1.0f / D);
    float rs = rsqrtf(var + 1e-8f);

    out[(size_t)row * DP + d] =
        (d < D) ? (diff * rs * g[d] + bln[d] + resid[(size_t)row * DP + d]) : 0.0f;
}

// ---------------- unpad copy to output ----------------
__global__ void __launch_bounds__(256) copyout_kernel(const float* __restrict__ X,
                                                      float* __restrict__ out) {
    int n = blockIdx.x, d = threadIdx.x;
    if (d < D) out[(size_t)n * D + d] = X[(size_t)n * DP + d];
}

// ---------------- launch ----------------
extern "C" void kernel_launch(void* const* d_in, const int* in_sizes, int n_in,
                              void* d_out, int out_size) {
    const int*   tokens = (const int*)d_in[0];
    const float* emb    = (const float*)d_in[1];
    const float* Wq = (const float*)d_in[2],  *bq = (const float*)d_in[3];
    const float* Wk = (const float*)d_in[4],  *bk = (const float*)d_in[5];
    const float* Wv = (const float*)d_in[6],  *bv = (const float*)d_in[7];
    const float* W1 = (const float*)d_in[8],  *b1 = (const float*)d_in[9];
    const float* W2 = (const float*)d_in[10], *b2 = (const float*)d_in[11];
    const float* lng = (const float*)d_in[12], *lnb = (const float*)d_in[13];
    float* out = (float*)d_out;

    float *X, *Y, *Q, *K, *V, *Wp;
    cudaGetSymbolAddress((void**)&X, g_X);
    cudaGetSymbolAddress((void**)&Y, g_Y);
    cudaGetSymbolAddress((void**)&Q, g_Q);
    cudaGetSymbolAddress((void**)&K, g_K);
    cudaGetSymbolAddress((void**)&V, g_V);
    cudaGetSymbolAddress((void**)&Wp, g_W);

    const int attn_smem = (10000 + 10000 + 50 * 52 + 64) * 4;  // ~90.7 KB
    cudaFuncSetAttribute(attn_kernel, cudaFuncAttributeMaxDynamicSharedMemorySize,
                         96 * 1024);

    embed_kernel<<<NTOK, 256>>>(tokens, emb, X);
    pad_w_kernel<<<dim3(15, 256), 256>>>(Wq, Wk, Wv, W1, W2, Wp);

    dim3 ggrid(DP / 128, NTOK / 128);   // (2, 1600)
    for (int i = 0; i < NB; i++) {
        float* wq = Wp + (size_t)(i * 5 + 0) * DP * DP;
        float* wk = Wp + (size_t)(i * 5 + 1) * DP * DP;
        float* wv = Wp + (size_t)(i * 5 + 2) * DP * DP;
        float* w1 = Wp + (size_t)(i * 5 + 3) * DP * DP;
        float* w2 = Wp + (size_t)(i * 5 + 4) * DP * DP;

        gemm_kernel<<<ggrid, 256>>>(X, wq, bq + i * D, Q, 1);
        gemm_kernel<<<ggrid, 256>>>(X, wk, bk + i * D, K, 1);
        gemm_kernel<<<ggrid, 256>>>(X, wv, bv + i * D, V, 1);
        attn_kernel<<<BATCH, 256, attn_smem>>>(Q, K, V, X, Y);
        gemm_kernel<<<ggrid, 256>>>(Y, w1, b1 + i * D, V, 1);   // h1 -> V
        gemm_kernel<<<ggrid, 256>>>(V, w2, b2 + i * D, Q, 0);   // h2 -> Q
        ln_res_kernel<<<NTOK, 256>>>(Q, Y, lng + i * D, lnb + i * D, X);
    }

    copyout_kernel<<<NTOK, 256>>>(X, out);
}